// round 6
// baseline (speedup 1.0000x reference)
#include <cuda_runtime.h>
#include <cuda_bf16.h>
#include <cstdint>

#define N_QUERIES 262144
#define N_SLOTS   1024
#define KEY_DIM   64
#define VAL_DIM   64
#define TOPK      4
#define LR        0.001f
#define MOMENTUM  0.9f
#define WD        0.0001f

#define RET_ELEMS  (N_QUERIES * TOPK * VAL_DIM)   // 67108864
#define SLOT_ELEMS (N_SLOTS * VAL_DIM)            // 65536
#define QPC 256                                   // queries per CTA
#define NC6 6                                     // candidates per thread/query

typedef unsigned int u32;

// ---------------- scratch (device globals; no allocation allowed) -----------
__device__ int   g_idx[N_QUERIES * TOPK];                          // 4 MB
__device__ __align__(16) float g_sg[SLOT_ELEMS];
__device__ float g_cnt[N_SLOTS];
__device__ __align__(16) __nv_bfloat16 g_qbf[N_QUERIES * KEY_DIM]; // 32 MB swizzled rows
__device__ __align__(16) __nv_bfloat16 g_kbf[N_SLOTS * KEY_DIM];   // 128 KB swizzled rows

// row layout: 128 bytes/row; 16B-chunk uc stored at byte ((uc ^ (row&7))<<4)
__device__ __host__ __forceinline__ int swz_byte(int row_and7, int kbyte) {
    return ((kbyte & ~15) ^ (row_and7 << 4)) | (kbyte & 15);
}

// ---------------- kernel 0: pack Q/K to swizzled bf16 + zero accumulators ---
__global__ void prep_kernel(const float* __restrict__ queries,
                            const float* __restrict__ keys) {
    int i = blockIdx.x * 256 + threadIdx.x;
    if (i < 2097152 + 8192) {
        const float* src;
        __nv_bfloat16* dst;
        int row, uc;
        if (i < 2097152) { row = i >> 3; uc = i & 7; src = queries; dst = g_qbf; }
        else { int j = i - 2097152; row = j >> 3; uc = j & 7; src = keys; dst = g_kbf; }
        const float4* in4 = (const float4*)(src + (size_t)row * 64 + uc * 8);
        float4 a = in4[0], b = in4[1];
        __nv_bfloat162 p0 = __float22bfloat162_rn(make_float2(a.x, a.y));
        __nv_bfloat162 p1 = __float22bfloat162_rn(make_float2(a.z, a.w));
        __nv_bfloat162 p2 = __float22bfloat162_rn(make_float2(b.x, b.y));
        __nv_bfloat162 p3 = __float22bfloat162_rn(make_float2(b.z, b.w));
        int byte = (row & 7) ^ uc;                 // chunk index after swizzle
        uint4* out = (uint4*)((char*)dst + (size_t)row * 128 + byte * 16);
        *out = make_uint4(*(u32*)&p0, *(u32*)&p1, *(u32*)&p2, *(u32*)&p3);
    } else {
        int j = i - (2097152 + 8192);
        if (j < SLOT_ELEMS) g_sg[j] = 0.0f;
        if (j < N_SLOTS)    g_cnt[j] = 0.0f;
    }
}

// ---------------- mma.sync bf16 (legacy tensor-core path, compute_103-legal)
__device__ __forceinline__ void mma16816(float* d, const u32* a, const u32* b) {
    asm volatile(
        "mma.sync.aligned.m16n8k16.row.col.f32.bf16.bf16.f32 "
        "{%0,%1,%2,%3}, {%4,%5,%6,%7}, {%8,%9}, {%0,%1,%2,%3};"
        : "+f"(d[0]), "+f"(d[1]), "+f"(d[2]), "+f"(d[3])
        : "r"(a[0]), "r"(a[1]), "r"(a[2]), "r"(a[3]), "r"(b[0]), "r"(b[1]));
}

// ---------------- kernel 1: HMMA sim filter + exact top-4 + gather ----------
// SMEM map (bytes):
#define OFF_Q    0          // 256 x 128B = 32 KB
#define OFF_K    32768      // 1024 x 128B = 128 KB
#define OFF_MV   163840     // merge vals: 256 q x 16 x f32 = 16 KB
#define OFF_MI   180224     // merge idx : 16 KB
#define OFF_FI   196608     // final idx : 256 q x 4 int = 4 KB
#define SMEM_SZ  200704

__global__ void __launch_bounds__(256, 1)
simtopk_kernel(const float* __restrict__ queries,
               const float* __restrict__ keys,
               const float* __restrict__ vals,
               float* __restrict__ retrieved) {
    extern __shared__ char smem[];
    const int tid  = threadIdx.x;
    const int wid  = tid >> 5, lane = tid & 31;
    const int g    = lane >> 2, tig = lane & 3;
    const int qbase = blockIdx.x * QPC;
    const int qw    = wid * 32;                    // warp's local query base

    // stage Q tile (32 KB) + K (128 KB): straight uint4 copies (pre-swizzled)
    {
        const uint4* qs = (const uint4*)(g_qbf + (size_t)qbase * KEY_DIM);
        uint4* qd = (uint4*)(smem + OFF_Q);
        for (int i = tid; i < 2048; i += 256) qd[i] = qs[i];
        const uint4* ks = (const uint4*)g_kbf;
        uint4* kd = (uint4*)(smem + OFF_K);
        for (int i = tid; i < 8192; i += 256) kd[i] = ks[i];
    }
    __syncthreads();

    // ---- load A fragments: 2 row-sets (rows +0/+8 and +16/+24), 4 k-chunks
    u32 A[2][4][4];
#pragma unroll
    for (int s2 = 0; s2 < 2; s2++) {
#pragma unroll
        for (int kc = 0; kc < 4; kc++) {
            int r0 = qw + 16 * s2 + g;             // (r0 & 7) == g
            int r1 = r0 + 8;
            int c0 = ((kc * 2) ^ g) << 4;          // swizzled chunk byte
            int c1 = ((kc * 2 + 1) ^ g) << 4;
            A[s2][kc][0] = *(const u32*)(smem + OFF_Q + r0 * 128 + c0 + 4 * tig);
            A[s2][kc][1] = *(const u32*)(smem + OFF_Q + r1 * 128 + c0 + 4 * tig);
            A[s2][kc][2] = *(const u32*)(smem + OFF_Q + r0 * 128 + c1 + 4 * tig);
            A[s2][kc][3] = *(const u32*)(smem + OFF_Q + r1 * 128 + c1 + 4 * tig);
        }
    }

    // ---- main loop: per-thread local top-6 per query (4 queries/thread)
    float tv[4][NC6];
    u32   ti[4][NC6];
#pragma unroll
    for (int s = 0; s < 4; s++)
#pragma unroll
        for (int c = 0; c < NC6; c++) { tv[s][c] = -1e30f; ti[s][c] = 0; }

    const char* kb = smem + OFF_K + g * 128;       // B row n = nc*8+g
#pragma unroll 2
    for (int nc = 0; nc < 128; nc++) {
        float acc[8];
#pragma unroll
        for (int j = 0; j < 8; j++) acc[j] = 0.0f;
        const char* krow = kb + nc * 1024;
#pragma unroll
        for (int kc = 0; kc < 4; kc++) {
            u32 b[2];
            b[0] = *(const u32*)(krow + ((((kc * 2)     ^ g) << 4) | (4 * tig)));
            b[1] = *(const u32*)(krow + ((((kc * 2 + 1) ^ g) << 4) | (4 * tig)));
            mma16816(acc,     A[0][kc], b);
            mma16816(acc + 4, A[1][kc], b);
        }
        const u32 n0 = nc * 8 + 2 * tig;
#pragma unroll
        for (int s = 0; s < 4; s++) {
#pragma unroll
            for (int h = 0; h < 2; h++) {
                float v = acc[(s >> 1) * 4 + (s & 1) * 2 + h];
                // acc mapping: s0:c0,c1 | s1:c2,c3 | s2:c4,c5 | s3:c6,c7
                u32 jg = n0 + h;
                if (v > tv[s][5]) {                 // sorted insert into top-6
                    tv[s][5] = v; ti[s][5] = jg;
#pragma unroll
                    for (int c = 5; c > 0; c--) {
                        if (tv[s][c] > tv[s][c - 1]) {
                            float tf = tv[s][c]; tv[s][c] = tv[s][c - 1]; tv[s][c - 1] = tf;
                            u32 tg2 = ti[s][c]; ti[s][c] = ti[s][c - 1]; ti[s][c - 1] = tg2;
                        }
                    }
                }
            }
        }
    }

    // ---- exact recheck per query, publish per-thread top-4 to merge smem ---
    float* mval = (float*)(smem + OFF_MV);
    int*   midx = (int*)(smem + OFF_MI);
#pragma unroll 1
    for (int s = 0; s < 4; s++) {
        int ci[NC6];
#pragma unroll
        for (int c = 0; c < NC6; c++) ci[c] = (int)ti[s][c];
        // sort indices ascending (odd-even transposition, 6 rounds)
#pragma unroll
        for (int rnd = 0; rnd < 6; rnd++) {
#pragma unroll
            for (int p = (rnd & 1); p < 5; p += 2)
                if (ci[p] > ci[p + 1]) { int t = ci[p]; ci[p] = ci[p + 1]; ci[p + 1] = t; }
        }
        // sequential fp32 chains (reference accumulation order)
        const int qrow = qbase + qw + g + 8 * s;
        float accx[NC6];
#pragma unroll
        for (int c = 0; c < NC6; c++) accx[c] = 0.0f;
        const float4* qr = (const float4*)(queries + (size_t)qrow * KEY_DIM);
#pragma unroll
        for (int ch = 0; ch < 16; ch++) {
            float4 qc = __ldg(qr + ch);
#pragma unroll
            for (int c = 0; c < NC6; c++) {
                float4 kk = __ldg((const float4*)(keys + (size_t)ci[c] * KEY_DIM) + ch);
                float a = accx[c];
                a = fmaf(qc.x, kk.x, a);
                a = fmaf(qc.y, kk.y, a);
                a = fmaf(qc.z, kk.z, a);
                a = fmaf(qc.w, kk.w, a);
                accx[c] = a;
            }
        }
        // exact top-4 of 6, ascending index + strict > => stable ties
        float bv[4] = {-1e30f, -1e30f, -1e30f, -1e30f};
        int   bi[4] = {0, 0, 0, 0};
#pragma unroll
        for (int c = 0; c < NC6; c++) {
            float v = accx[c]; int id = ci[c];
            if (v > bv[3]) {
                if (v > bv[0]) {
                    bv[3]=bv[2]; bi[3]=bi[2]; bv[2]=bv[1]; bi[2]=bi[1];
                    bv[1]=bv[0]; bi[1]=bi[0]; bv[0]=v;    bi[0]=id;
                } else if (v > bv[1]) {
                    bv[3]=bv[2]; bi[3]=bi[2]; bv[2]=bv[1]; bi[2]=bi[1];
                    bv[1]=v;     bi[1]=id;
                } else if (v > bv[2]) {
                    bv[3]=bv[2]; bi[3]=bi[2]; bv[2]=v;    bi[2]=id;
                } else { bv[3]=v; bi[3]=id; }
            }
        }
        const int qidx = qw + g + 8 * s;           // local query 0..255
#pragma unroll
        for (int r = 0; r < 4; r++) {
            mval[qidx * 16 + tig * 4 + r] = bv[r];
            midx[qidx * 16 + tig * 4 + r] = bi[r];
        }
    }
    __syncwarp();

    // ---- merge 4 threads x top-4 -> global top-4 (val desc, idx asc) -------
    int* fidx = (int*)(smem + OFF_FI);
    {
        const int qidx = qw + lane;                // lane m merges query m
        float v[16]; int id[16];
#pragma unroll
        for (int e = 0; e < 16; e++) {
            v[e] = mval[qidx * 16 + e];
            id[e] = midx[qidx * 16 + e];
        }
#pragma unroll
        for (int r = 0; r < 4; r++) {
            int best = 0;
#pragma unroll
            for (int e = 1; e < 16; e++) {
                bool better = (v[e] > v[best]) ||
                              (v[e] == v[best] && id[e] < id[best]);
                if (better) best = e;
            }
            fidx[qidx * 4 + r] = id[best];
            g_idx[(qbase + qidx) * TOPK + r] = id[best];
            v[best] = -1e31f;
        }
    }
    __syncwarp();

    // ---- cooperative gather of retrieved rows (coalesced) ------------------
    for (int q = 0; q < 32; q++) {
        const int qidx = qw + q;
        float4* out4 = (float4*)(retrieved + (size_t)(qbase + qidx) * (TOPK * VAL_DIM));
#pragma unroll
        for (int half = 0; half < 2; half++) {
            int j  = lane + half * 32;             // 0..63
            int r  = j >> 4;
            int e  = j & 15;
            int id = fidx[qidx * 4 + r];
            out4[j] = __ldg((const float4*)(vals + (size_t)id * VAL_DIM) + e);
        }
    }
}

// ---------------- kernel 2: scatter grads via direct global v4 reductions ---
#define W_TOTAL (RET_ELEMS / 4)
#define SCAT_THREADS (2048 * 256)
__global__ void __launch_bounds__(256)
scatter_kernel(const float4* __restrict__ grads4) {
    int t = blockIdx.x * 256 + threadIdx.x;
#pragma unroll 4
    for (int it = 0; it < W_TOTAL / SCAT_THREADS; it++) {
        int w    = t + it * SCAT_THREADS;
        int e    = w >> 4;
        int c4   = w & 15;
        int slot = __ldg(&g_idx[e]);
        float4 gg = __ldg(&grads4[w]);
        float* dst = &g_sg[slot * VAL_DIM + c4 * 4];
        asm volatile("red.global.add.v4.f32 [%0], {%1, %2, %3, %4};"
                     :: "l"(dst), "f"(gg.x), "f"(gg.y), "f"(gg.z), "f"(gg.w)
                     : "memory");
        if (c4 == 0) atomicAdd(&g_cnt[slot], 1.0f);
    }
}

// ---------------- kernel 3: finalize vals_new / mom_new ---------------------
__global__ void finalize_kernel(const float* __restrict__ vals,
                                const float* __restrict__ mom,
                                float* __restrict__ out) {
    int i = blockIdx.x * blockDim.x + threadIdx.x;
    if (i >= SLOT_ELEMS) return;
    int   slot = i >> 6;
    float c    = g_cnt[slot];
    float sgv  = g_sg[i];
    bool  nz   = c > 0.0f;
    float avg  = nz ? (sgv / c) : sgv;
    float mn   = MOMENTUM * mom[i] + avg;
    float delta = -LR * (mn + WD * vals[i]);
    float vn   = vals[i] + (nz ? delta : 0.0f);
    out[RET_ELEMS + i]              = vn;
    out[RET_ELEMS + SLOT_ELEMS + i] = mn;
}

// ---------------- launch ----------------------------------------------------
extern "C" void kernel_launch(void* const* d_in, const int* in_sizes, int n_in,
                              void* d_out, int out_size) {
    const float* queries = (const float*)d_in[0];
    const float* keys    = (const float*)d_in[1];
    const float* vals    = (const float*)d_in[2];
    const float* mom     = (const float*)d_in[3];
    const float* grads   = (const float*)d_in[4];
    float* out = (float*)d_out;

    static bool attr_set = false;
    if (!attr_set) {
        cudaFuncSetAttribute(simtopk_kernel,
                             cudaFuncAttributeMaxDynamicSharedMemorySize,
                             SMEM_SZ);
        attr_set = true;
    }

    prep_kernel<<<8480, 256>>>(queries, keys);
    simtopk_kernel<<<N_QUERIES / QPC, 256, SMEM_SZ>>>(queries, keys, vals, out);
    scatter_kernel<<<2048, 256>>>((const float4*)grads);
    finalize_kernel<<<256, 256>>>(vals, mom, out);
}

// round 11
// speedup vs baseline: 1.2914x; 1.2914x over previous
#include <cuda_runtime.h>
#include <cstdint>

#define N_QUERIES 262144
#define N_SLOTS   1024
#define KEY_DIM   64
#define VAL_DIM   64
#define TOPK      4
#define LR        0.001f
#define MOMENTUM  0.9f
#define WD        0.0001f

#define RET_ELEMS  (N_QUERIES * TOPK * VAL_DIM)   // 67108864
#define SLOT_ELEMS (N_SLOTS * VAL_DIM)            // 65536
#define NC 12                                     // candidates per query

typedef unsigned int u32;

__device__ __forceinline__ int dp4a_s(int a, int b, int c) {
    int d;
    asm("dp4a.s32.s32 %0, %1, %2, %3;" : "=r"(d) : "r"(a), "r"(b), "r"(c));
    return d;
}

// ---------------- scratch (device globals; no allocation allowed) -----------
__device__ int   g_idx[N_QUERIES * TOPK];                 // 4 MB
__device__ __align__(16) float g_sg[SLOT_ELEMS];
__device__ float g_cnt[N_SLOTS];
__device__ __align__(16) int4 g_k8[N_SLOTS * 4];          // int8 keys, 64 KB
__device__ float g_ksc[N_SLOTS];                          // per-slot dequant scale

// ---------------- kernel 0: quantize keys + zero accumulators ---------------
__global__ void prep_kernel(const float* __restrict__ keys) {
    int i = blockIdx.x * 256 + threadIdx.x;    // 65536 threads
    if (i < SLOT_ELEMS) g_sg[i] = 0.0f;
    if (i < N_SLOTS) {
        g_cnt[i] = 0.0f;
        const float* kr = keys + (size_t)i * KEY_DIM;
        float mx = 0.0f;
#pragma unroll
        for (int d = 0; d < KEY_DIM; d++) mx = fmaxf(mx, fabsf(kr[d]));
        mx = fmaxf(mx, 1e-30f);
        float sc = 127.0f / mx;
        g_ksc[i] = mx * (1.0f / 127.0f);
#pragma unroll
        for (int c = 0; c < 4; c++) {
            int w[4];
#pragma unroll
            for (int wi = 0; wi < 4; wi++) {
                int d0 = c * 16 + wi * 4;
                int b0 = __float2int_rn(kr[d0 + 0] * sc) & 0xFF;
                int b1 = __float2int_rn(kr[d0 + 1] * sc) & 0xFF;
                int b2 = __float2int_rn(kr[d0 + 2] * sc) & 0xFF;
                int b3 = __float2int_rn(kr[d0 + 3] * sc) & 0xFF;
                w[wi] = b0 | (b1 << 8) | (b2 << 16) | (b3 << 24);
            }
            g_k8[i * 4 + c] = make_int4(w[0], w[1], w[2], w[3]);
        }
    }
}

// ---------------- kernel 1: dp4a sim filter + exact top-4 + gather ----------
// 1 query per lane; 256 queries per CTA. Keys (int8, 64 KB) + scales in SMEM,
// read as 128-bit warp-uniform broadcasts. Per-lane sorted top-12 approx
// candidates, then exact sequential-fp32 recheck (reference accumulation
// order, ascending-index, strict-> tie-break).
#define SMEM_K8   0                     // 65536 B
#define SMEM_KSC  65536                 // 4096 B
#define SMEM_FIDX 69632                 // 256*4 int = 4096 B
#define SMEM_SZ   73728

__global__ void __launch_bounds__(256, 2)
simtopk_kernel(const float* __restrict__ queries,
               const float* __restrict__ keys,
               const float* __restrict__ vals,
               float* __restrict__ retrieved) {
    extern __shared__ char smem[];
    int4*  sk8  = (int4*)(smem + SMEM_K8);
    float* sksc = (float*)(smem + SMEM_KSC);
    int*   sfid = (int*)(smem + SMEM_FIDX);

    const int tid  = threadIdx.x;
    const int wid  = tid >> 5, lane = tid & 31;
    const int q    = blockIdx.x * 256 + tid;

    // stage keys + scales
    for (int t = tid; t < N_SLOTS * 4; t += 256) sk8[t] = g_k8[t];
    for (int t = tid; t < N_SLOTS; t += 256) sksc[t] = g_ksc[t];

    // quantize own query in-register (pass 1: max, pass 2: pack; L1 hit)
    const float4* qr = (const float4*)(queries + (size_t)q * KEY_DIM);
    float mx = 0.0f;
#pragma unroll
    for (int c = 0; c < 16; c++) {
        float4 v = __ldg(qr + c);
        mx = fmaxf(mx, fmaxf(fmaxf(fabsf(v.x), fabsf(v.y)),
                             fmaxf(fabsf(v.z), fabsf(v.w))));
    }
    mx = fmaxf(mx, 1e-30f);
    const float qsc  = 127.0f / mx;
    const float qinv = mx * (1.0f / 127.0f);
    int qi[16];
#pragma unroll
    for (int c = 0; c < 16; c++) {
        float4 v = __ldg(qr + c);
        int b0 = __float2int_rn(v.x * qsc) & 0xFF;
        int b1 = __float2int_rn(v.y * qsc) & 0xFF;
        int b2 = __float2int_rn(v.z * qsc) & 0xFF;
        int b3 = __float2int_rn(v.w * qsc) & 0xFF;
        qi[c] = b0 | (b1 << 8) | (b2 << 16) | (b3 << 24);
    }
    __syncthreads();

    // ---- scan all 1024 slots, keep sorted top-12 --------------------------
    float tv[NC];
    int   ti[NC];
#pragma unroll
    for (int c = 0; c < NC; c++) { tv[c] = -1e30f; ti[c] = 0; }

#pragma unroll 2
    for (int j = 0; j < N_SLOTS; j++) {
        int4 k0 = sk8[j * 4 + 0];
        int4 k1 = sk8[j * 4 + 1];
        int4 k2 = sk8[j * 4 + 2];
        int4 k3 = sk8[j * 4 + 3];
        int a0 = 0, a1 = 0, a2 = 0, a3 = 0;
        a0 = dp4a_s(k0.x, qi[0],  a0); a0 = dp4a_s(k0.y, qi[1],  a0);
        a0 = dp4a_s(k0.z, qi[2],  a0); a0 = dp4a_s(k0.w, qi[3],  a0);
        a1 = dp4a_s(k1.x, qi[4],  a1); a1 = dp4a_s(k1.y, qi[5],  a1);
        a1 = dp4a_s(k1.z, qi[6],  a1); a1 = dp4a_s(k1.w, qi[7],  a1);
        a2 = dp4a_s(k2.x, qi[8],  a2); a2 = dp4a_s(k2.y, qi[9],  a2);
        a2 = dp4a_s(k2.z, qi[10], a2); a2 = dp4a_s(k2.w, qi[11], a2);
        a3 = dp4a_s(k3.x, qi[12], a3); a3 = dp4a_s(k3.y, qi[13], a3);
        a3 = dp4a_s(k3.z, qi[14], a3); a3 = dp4a_s(k3.w, qi[15], a3);
        int idot = (a0 + a1) + (a2 + a3);
        float v = (float)idot * (qinv * sksc[j]);
        if (v > tv[NC - 1]) {
            tv[NC - 1] = v; ti[NC - 1] = j;
#pragma unroll
            for (int c = NC - 1; c > 0; c--) {
                if (tv[c] > tv[c - 1]) {
                    float tf = tv[c]; tv[c] = tv[c - 1]; tv[c - 1] = tf;
                    int   tg = ti[c]; ti[c] = ti[c - 1]; ti[c - 1] = tg;
                }
            }
        }
    }

    // ---- exact recheck: indices ascending, sequential fp32 chains ----------
    int ci[NC];
#pragma unroll
    for (int c = 0; c < NC; c++) ci[c] = ti[c];
#pragma unroll
    for (int rnd = 0; rnd < NC; rnd++)
#pragma unroll
        for (int p = (rnd & 1); p < NC - 1; p += 2)
            if (ci[p] > ci[p + 1]) { int t = ci[p]; ci[p] = ci[p + 1]; ci[p + 1] = t; }

    float accx[NC];
#pragma unroll
    for (int c = 0; c < NC; c++) accx[c] = 0.0f;
#pragma unroll
    for (int ch = 0; ch < 16; ch++) {
        float4 qc = __ldg(qr + ch);
#pragma unroll
        for (int c = 0; c < NC; c++) {
            float4 kk = __ldg((const float4*)(keys + (size_t)ci[c] * KEY_DIM) + ch);
            float a = accx[c];
            a = fmaf(qc.x, kk.x, a);
            a = fmaf(qc.y, kk.y, a);
            a = fmaf(qc.z, kk.z, a);
            a = fmaf(qc.w, kk.w, a);
            accx[c] = a;
        }
    }
    // top-4 of 12: ascending index + strict > => stable ties
    float bv[4] = {-1e30f, -1e30f, -1e30f, -1e30f};
    int   bi[4] = {0, 0, 0, 0};
#pragma unroll
    for (int c = 0; c < NC; c++) {
        float v = accx[c]; int id = ci[c];
        if (v > bv[3]) {
            if (v > bv[0]) {
                bv[3]=bv[2]; bi[3]=bi[2]; bv[2]=bv[1]; bi[2]=bi[1];
                bv[1]=bv[0]; bi[1]=bi[0]; bv[0]=v;    bi[0]=id;
            } else if (v > bv[1]) {
                bv[3]=bv[2]; bi[3]=bi[2]; bv[2]=bv[1]; bi[2]=bi[1];
                bv[1]=v;     bi[1]=id;
            } else if (v > bv[2]) {
                bv[3]=bv[2]; bi[3]=bi[2]; bv[2]=v;    bi[2]=id;
            } else { bv[3]=v; bi[3]=id; }
        }
    }

#pragma unroll
    for (int r = 0; r < 4; r++) {
        g_idx[q * TOPK + r] = bi[r];
        sfid[tid * 4 + r]   = bi[r];
    }
    __syncwarp();

    // ---- cooperative coalesced gather of retrieved rows --------------------
    const int qw = wid * 32;
    for (int qq = 0; qq < 32; qq++) {
        const int qloc = qw + qq;
        float4* out4 =
            (float4*)(retrieved + (size_t)(blockIdx.x * 256 + qloc) * (TOPK * VAL_DIM));
#pragma unroll
        for (int half = 0; half < 2; half++) {
            int j  = lane + half * 32;          // 0..63
            int r  = j >> 4;
            int e  = j & 15;
            int id = sfid[qloc * 4 + r];
            out4[j] = __ldg((const float4*)(vals + (size_t)id * VAL_DIM) + e);
        }
    }
}

// ---------------- kernel 2: scatter grads via direct global v4 reductions ---
#define W_TOTAL (RET_ELEMS / 4)
#define SCAT_THREADS (2048 * 256)
__global__ void __launch_bounds__(256)
scatter_kernel(const float4* __restrict__ grads4) {
    int t = blockIdx.x * 256 + threadIdx.x;
#pragma unroll 4
    for (int it = 0; it < W_TOTAL / SCAT_THREADS; it++) {
        int w    = t + it * SCAT_THREADS;
        int e    = w >> 4;
        int c4   = w & 15;
        int slot = __ldg(&g_idx[e]);
        float4 gg = __ldg(&grads4[w]);
        float* dst = &g_sg[slot * VAL_DIM + c4 * 4];
        asm volatile("red.global.add.v4.f32 [%0], {%1, %2, %3, %4};"
                     :: "l"(dst), "f"(gg.x), "f"(gg.y), "f"(gg.z), "f"(gg.w)
                     : "memory");
        if (c4 == 0) atomicAdd(&g_cnt[slot], 1.0f);
    }
}

// ---------------- kernel 3: finalize vals_new / mom_new ---------------------
__global__ void finalize_kernel(const float* __restrict__ vals,
                                const float* __restrict__ mom,
                                float* __restrict__ out) {
    int i = blockIdx.x * blockDim.x + threadIdx.x;
    if (i >= SLOT_ELEMS) return;
    int   slot = i >> 6;
    float c    = g_cnt[slot];
    float sgv  = g_sg[i];
    bool  nz   = c > 0.0f;
    float avg  = nz ? (sgv / c) : sgv;
    float mn   = MOMENTUM * mom[i] + avg;
    float delta = -LR * (mn + WD * vals[i]);
    float vn   = vals[i] + (nz ? delta : 0.0f);
    out[RET_ELEMS + i]              = vn;
    out[RET_ELEMS + SLOT_ELEMS + i] = mn;
}

// ---------------- launch ----------------------------------------------------
extern "C" void kernel_launch(void* const* d_in, const int* in_sizes, int n_in,
                              void* d_out, int out_size) {
    const float* queries = (const float*)d_in[0];
    const float* keys    = (const float*)d_in[1];
    const float* vals    = (const float*)d_in[2];
    const float* mom     = (const float*)d_in[3];
    const float* grads   = (const float*)d_in[4];
    float* out = (float*)d_out;

    static bool attr_set = false;
    if (!attr_set) {
        cudaFuncSetAttribute(simtopk_kernel,
                             cudaFuncAttributeMaxDynamicSharedMemorySize,
                             SMEM_SZ);
        attr_set = true;
    }

    prep_kernel<<<256, 256>>>(keys);
    simtopk_kernel<<<N_QUERIES / 256, 256, SMEM_SZ>>>(queries, keys, vals, out);
    scatter_kernel<<<2048, 256>>>((const float4*)grads);
    finalize_kernel<<<256, 256>>>(vals, mom, out);
}